// round 8
// baseline (speedup 1.0000x reference)
#include <cuda_runtime.h>

#define NQ      10
#define DIM     1024
#define TSTEPS  10
#define NDATA   1024
#define NTHREADS 128               // 4 warps = 1 sample
#define AMPS    8

typedef unsigned long long u64;

__device__ __forceinline__ u64 pk(float x, float y) {
    u64 u; asm("mov.b64 %0, {%1,%2};" : "=l"(u) : "f"(x), "f"(y)); return u;
}
__device__ __forceinline__ void upk(u64 u, float &x, float &y) {
    asm("mov.b64 {%0,%1}, %2;" : "=f"(x), "=f"(y) : "l"(u));
}
__device__ __forceinline__ u64 swp(u64 u) { float x, y; upk(u, x, y); return pk(y, x); }
__device__ __forceinline__ u64 ffma2(u64 a, u64 b, u64 c) {
    u64 d; asm("fma.rn.f32x2 %0, %1, %2, %3;" : "=l"(d) : "l"(a), "l"(b), "l"(c)); return d;
}
__device__ __forceinline__ u64 fmul2(u64 a, u64 b) {
    u64 d; asm("mul.rn.f32x2 %0, %1, %2;" : "=l"(d) : "l"(a), "l"(b)); return d;
}

// amp j = (w<<8)|(lh<<6)|(a<<3)|b ; qubit i <-> j bit (9-i)
// Layout A: thread(lane=(lh<<3)|ll) reg r holds amp(a=r, b=ll)  [reg qubits 4,5,6]
// Layout B: thread(lane=(lh<<3)|ll) reg r holds amp(a=ll, b=r)  [reg qubits 7,8,9]
// Canonical swizzled smem slot for amp (w,lh,a,b): (w<<8)|(lh<<6)|((b^lh)<<3)|(a^b)

__global__ __launch_bounds__(NTHREADS)
void scramble_kernel(const float* __restrict__ in_re,
                     const float* __restrict__ in_im,
                     const float* __restrict__ phis,
                     const float* __restrict__ gs,
                     float* __restrict__ out)
{
    __shared__ u64    s_x[2][DIM];            // double-buffered exchange
    __shared__ float2 s_rot[TSTEPS * NQ];     // (cos(th/2), sin(th/2))
    __shared__ float  s_wgt[11][NQ];          // merged diag weights
    __shared__ float  s_lane[11 * 32];        // layout-aware lane sums
    __shared__ float  s_rphi[11 * 8 * 11];    // layout-aware reg sums + popcount phase
    __shared__ float  s_w[11 * 4];            // w sums + (-0.5*total)
    __shared__ float  s_nrm[4];

    const int tid  = threadIdx.x;
    const int w    = tid >> 5;
    const int lane = tid & 31;
    const int lh   = lane >> 3;
    const int ll   = lane & 7;
    const int b    = blockIdx.x;
    const float* P = phis + b * 300;

    // ---- rotation coefficients ----
    if (tid < 100) {
        int tt = tid / NQ, i = tid - tt * NQ;
        float th = P[30 * tt + NQ + i];
        float s, c; __sincosf(0.5f * th, &s, &c);
        s_rot[tid] = make_float2(c, s);
    }
    // ---- merged diag weights w_i(t) = a_i(t) + b_i(t-1) ----
    if (tid < 110) {
        int tt = tid / NQ, i = tid - tt * NQ;
        float v = 0.f;
        if (tt < 10) v += P[30 * tt + i];
        if (tt > 0)  v += P[30 * (tt - 1) + 2 * NQ + i];
        s_wgt[tt][i] = v;
    }
    __syncthreads();
    // ---- lane-sum tables (layout at diag of step tt: A if tt even) ----
    for (int idx = tid; idx < 11 * 32; idx += NTHREADS) {
        int tt = idx >> 5, l = idx & 31, la = tt & 1;
        float s = 0.f;
        if (l & 16) s += s_wgt[tt][2];
        if (l & 8)  s += s_wgt[tt][3];
        if (la == 0) {   // A: lane low bits = b-field -> qubits 7,8,9
            if (l & 4) s += s_wgt[tt][7];
            if (l & 2) s += s_wgt[tt][8];
            if (l & 1) s += s_wgt[tt][9];
        } else {         // B: lane low bits = a-field -> qubits 4,5,6
            if (l & 4) s += s_wgt[tt][4];
            if (l & 2) s += s_wgt[tt][5];
            if (l & 1) s += s_wgt[tt][6];
        }
        s_lane[idx] = s;
    }
    // ---- w-sum tables ----
    for (int idx = tid; idx < 11 * 4; idx += NTHREADS) {
        int tt = idx >> 2, ww = idx & 3;
        float tot = 0.f;
        #pragma unroll
        for (int i = 0; i < NQ; i++) tot += s_wgt[tt][i];
        float s = -0.5f * tot;
        if (ww & 1) s += s_wgt[tt][1];
        if (ww & 2) s += s_wgt[tt][0];
        s_w[idx] = s;
    }
    // ---- reg-sum + popcount-phase tables ----
    for (int idx = tid; idx < 11 * 8 * 11; idx += NTHREADS) {
        int tt = idx / 88, rem = idx - tt * 88;
        int r = rem / 11, k = rem - r * 11, la = tt & 1;
        float v = 0.f;
        if (la == 0) {   // A: r = a-field -> qubits 4,5,6
            if (r & 4) v += s_wgt[tt][4];
            if (r & 2) v += s_wgt[tt][5];
            if (r & 1) v += s_wgt[tt][6];
        } else {         // B: r = b-field -> qubits 7,8,9
            if (r & 4) v += s_wgt[tt][7];
            if (r & 2) v += s_wgt[tt][8];
            if (r & 1) v += s_wgt[tt][9];
        }
        if (tt > 0) {
            const float inv = 0.15811388300841897f;  // 1/(2*sqrt(10))
            float theta = gs[b * TSTEPS + tt - 1] * inv;
            float zs = 10.f - 2.f * (float)k;
            v += -0.5f * theta * (0.5f * (zs * zs - 10.f));
        }
        s_rphi[idx] = v;
    }

    // ---- load amplitudes (layout A) + norm ----
    u64 psi[AMPS];
    float nrm = 0.f;
    #pragma unroll
    for (int r = 0; r < AMPS; r++) {
        int j = (w << 8) | (lh << 6) | (r << 3) | ll;
        float re = in_re[b * DIM + j];
        float im = in_im[b * DIM + j];
        psi[r] = pk(re, im);
        nrm += re * re + im * im;
    }
    #pragma unroll
    for (int off = 16; off; off >>= 1)
        nrm += __shfl_xor_sync(0xFFFFFFFFu, nrm, off);
    if (lane == 0) s_nrm[w] = nrm;
    __syncthreads();                           // also fences table builds
    const float invn = rsqrtf(s_nrm[0] + s_nrm[1] + s_nrm[2] + s_nrm[3]);
    const int k0 = __popc(lane) + __popc(w);

    #pragma unroll 1
    for (int tt = 0; tt < TSTEPS; tt++) {
        // ---- diagonal E_tt (entry layout) ----
        {
            float base = s_lane[tt * 32 + lane] + s_w[tt * 4 + w];
            #pragma unroll
            for (int r = 0; r < AMPS; r++) {
                float ph = base + s_rphi[(tt * 8 + r) * 11 + k0 + __popc(r)];
                float sn, cn; __sincosf(ph, &sn, &cn);
                psi[r] = ffma2(pk(-sn, sn), swp(psi[r]), fmul2(pk(cn, cn), psi[r]));
            }
        }
        // ---- shuffle gates: qubits 2,3 (lane masks 16,8) ----
        #pragma unroll
        for (int q = 2; q < 4; q++) {
            const int m = 1 << (6 - q);
            float2 cs = s_rot[tt * NQ + q];
            float so = (lane & m) ? cs.y : -cs.y;
            u64 C2 = pk(cs.x, cs.x), S2 = pk(so, so);
            #pragma unroll
            for (int r = 0; r < AMPS; r++) {
                float x, y; upk(psi[r], x, y);
                float ox = __shfl_xor_sync(0xFFFFFFFFu, x, m);
                float oy = __shfl_xor_sync(0xFFFFFFFFu, y, m);
                psi[r] = ffma2(S2, pk(ox, oy), fmul2(C2, psi[r]));
            }
        }
        // ---- reg triple 1 (entry layout): qubits qb1..qb1+2, masks 4,2,1 ----
        const int qb1 = (tt & 1) ? 7 : 4;
        #pragma unroll
        for (int qq = 0; qq < 3; qq++) {
            const int m = 4 >> qq;
            float2 cs = s_rot[tt * NQ + qb1 + qq];
            u64 C2 = pk(cs.x, cs.x), S2 = pk(cs.y, cs.y), Sn = pk(-cs.y, -cs.y);
            #pragma unroll
            for (int rr = 0; rr < AMPS / 2; rr++) {
                int r0 = ((rr & ~(m - 1)) << 1) | (rr & (m - 1));
                int r1 = r0 | m;
                u64 p0 = psi[r0], p1 = psi[r1];
                psi[r0] = ffma2(Sn, p1, fmul2(C2, p0));
                psi[r1] = ffma2(S2, p0, fmul2(C2, p1));
            }
        }
        // ---- exchange qubit 0 (w mask 2) WITH layout flip ----
        {
            float2 cs = s_rot[tt * NQ + 0];
            // write under OLD layout: even tt -> A (a=r,b=ll): p=ll^lh,q=r^ll
            //                         odd  tt -> B (a=ll,b=r): p=r^lh, q=r^ll
            const int wbase = (w << 8) | (lh << 6);
            #pragma unroll
            for (int r = 0; r < AMPS; r++) {
                int p = (tt & 1) ? (r ^ lh) : (ll ^ lh);
                s_x[0][wbase | (p << 3) | (r ^ ll)] = psi[r];
            }
            __syncthreads();
            // read under NEW layout: even tt -> B: p=r^lh ; odd tt -> A: p=ll^lh
            float so = (w & 2) ? cs.y : -cs.y;
            u64 C2 = pk(cs.x, cs.x), S2 = pk(so, so);
            const int pbase = ((w ^ 2) << 8) | (lh << 6);
            #pragma unroll
            for (int r = 0; r < AMPS; r++) {
                int p = (tt & 1) ? (ll ^ lh) : (r ^ lh);
                int lo = (p << 3) | (r ^ ll);
                u64 own = s_x[0][wbase | lo];
                u64 par = s_x[0][pbase | lo];
                psi[r] = ffma2(S2, par, fmul2(C2, own));
            }
        }
        // ---- exchange qubit 1 (w mask 1), new layout, no flip ----
        {
            float2 cs = s_rot[tt * NQ + 1];
            const int wbase = (w << 8) | (lh << 6);
            #pragma unroll
            for (int r = 0; r < AMPS; r++) {
                int p = (tt & 1) ? (ll ^ lh) : (r ^ lh);
                s_x[1][wbase | (p << 3) | (r ^ ll)] = psi[r];
            }
            __syncthreads();
            float so = (w & 1) ? cs.y : -cs.y;
            u64 C2 = pk(cs.x, cs.x), S2 = pk(so, so);
            const int pbase = ((w ^ 1) << 8) | (lh << 6);
            #pragma unroll
            for (int r = 0; r < AMPS; r++) {
                int p = (tt & 1) ? (ll ^ lh) : (r ^ lh);
                u64 par = s_x[1][pbase | (p << 3) | (r ^ ll)];
                psi[r] = ffma2(S2, par, fmul2(C2, psi[r]));
            }
        }
        // ---- reg triple 2 (new layout): the other qubit triple ----
        const int qb2 = (tt & 1) ? 4 : 7;
        #pragma unroll
        for (int qq = 0; qq < 3; qq++) {
            const int m = 4 >> qq;
            float2 cs = s_rot[tt * NQ + qb2 + qq];
            u64 C2 = pk(cs.x, cs.x), S2 = pk(cs.y, cs.y), Sn = pk(-cs.y, -cs.y);
            #pragma unroll
            for (int rr = 0; rr < AMPS / 2; rr++) {
                int r0 = ((rr & ~(m - 1)) << 1) | (rr & (m - 1));
                int r1 = r0 | m;
                u64 p0 = psi[r0], p1 = psi[r1];
                psi[r0] = ffma2(Sn, p1, fmul2(C2, p0));
                psi[r1] = ffma2(S2, p0, fmul2(C2, p1));
            }
        }
    }

    // ---- final diagonal E_10 (layout A after 10 flips) ----
    {
        float base = s_lane[10 * 32 + lane] + s_w[10 * 4 + w];
        #pragma unroll
        for (int r = 0; r < AMPS; r++) {
            float ph = base + s_rphi[(10 * 8 + r) * 11 + k0 + __popc(r)];
            float sn, cn; __sincosf(ph, &sn, &cn);
            psi[r] = ffma2(pk(-sn, sn), swp(psi[r]), fmul2(pk(cn, cn), psi[r]));
        }
    }
    // ---- store (layout A) with deferred normalization ----
    #pragma unroll
    for (int r = 0; r < AMPS; r++) {
        int j = (w << 8) | (lh << 6) | (r << 3) | ll;
        float x, y; upk(psi[r], x, y);
        out[b * DIM + j]               = x * invn;
        out[NDATA * DIM + b * DIM + j] = y * invn;
    }
}

extern "C" void kernel_launch(void* const* d_in, const int* in_sizes, int n_in,
                              void* d_out, int out_size)
{
    const float* in_re = (const float*)d_in[0];
    const float* in_im = (const float*)d_in[1];
    const float* phis  = (const float*)d_in[2];
    const float* gs    = (const float*)d_in[3];
    float* out = (float*)d_out;
    scramble_kernel<<<NDATA, NTHREADS>>>(in_re, in_im, phis, gs, out);
}

// round 9
// speedup vs baseline: 1.0010x; 1.0010x over previous
#include <cuda_runtime.h>

#define NQ      10
#define DIM     1024
#define TSTEPS  10
#define NDATA   1024
#define NTHREADS 128               // 4 warps = 1 sample
#define AMPS    8

typedef unsigned long long u64;

__device__ __forceinline__ u64 pk(float x, float y) {
    u64 u; asm("mov.b64 %0, {%1,%2};" : "=l"(u) : "f"(x), "f"(y)); return u;
}
__device__ __forceinline__ void upk(u64 u, float &x, float &y) {
    asm("mov.b64 {%0,%1}, %2;" : "=f"(x), "=f"(y) : "l"(u));
}
__device__ __forceinline__ u64 swp(u64 u) { float x, y; upk(u, x, y); return pk(y, x); }
__device__ __forceinline__ u64 ffma2(u64 a, u64 b, u64 c) {
    u64 d; asm("fma.rn.f32x2 %0, %1, %2, %3;" : "=l"(d) : "l"(a), "l"(b), "l"(c)); return d;
}
__device__ __forceinline__ u64 fmul2(u64 a, u64 b) {
    u64 d; asm("mul.rn.f32x2 %0, %1, %2;" : "=l"(d) : "l"(a), "l"(b)); return d;
}

// amp j = (w<<8)|(lh<<6)|(a<<3)|b ; qubit i <-> j bit (9-i)
// Layout A: lane=(lh<<3)|ll, reg r holds amp(a=r, b=ll)  [reg qubits 4,5,6]
// Layout B: lane=(lh<<3)|ll, reg r holds amp(a=ll, b=r)  [reg qubits 7,8,9]
// Canonical swizzled smem slot for amp (w,lh,a,b): (w<<8)|(lh<<6)|((b^lh)<<3)|(a^b)

struct Ctx {
    u64*    s_x0;
    u64*    s_x1;
    float2* s_rot;
    float*  s_lane;
    float*  s_rphi;
    float*  s_w;
};

// One full time step, parity PAR (0: enters layout A, exits A-after-flip-chain)
template<int PAR>
__device__ __forceinline__ void do_step(int tt, u64 (&psi)[AMPS], const Ctx& C,
                                        int w, int lane, int lh, int ll, int k0)
{
    // ---- diagonal E_tt (entry layout; tables are layout-aware) ----
    {
        float base = C.s_lane[tt * 32 + lane] + C.s_w[tt * 4 + w];
        const float* rp = C.s_rphi + tt * 88 + k0;
        #pragma unroll
        for (int r = 0; r < AMPS; r++) {
            float ph = base + rp[r * 11 + __popc(r)];
            float sn, cn; __sincosf(ph, &sn, &cn);
            psi[r] = ffma2(pk(-sn, sn), swp(psi[r]), fmul2(pk(cn, cn), psi[r]));
        }
    }
    // ---- shuffle gates: qubits 2,3 (lane masks 16,8) ----
    #pragma unroll
    for (int q = 2; q < 4; q++) {
        const int m = 1 << (6 - q);
        float2 cs = C.s_rot[tt * NQ + q];
        float so = (lane & m) ? cs.y : -cs.y;
        u64 C2 = pk(cs.x, cs.x), S2 = pk(so, so);
        #pragma unroll
        for (int r = 0; r < AMPS; r++) {
            float x, y; upk(psi[r], x, y);
            float ox = __shfl_xor_sync(0xFFFFFFFFu, x, m);
            float oy = __shfl_xor_sync(0xFFFFFFFFu, y, m);
            psi[r] = ffma2(S2, pk(ox, oy), fmul2(C2, psi[r]));
        }
    }
    // ---- reg triple 1 (entry layout): qubits (PAR?7:4)+qq, masks 4,2,1 ----
    {
        const int qb1 = PAR ? 7 : 4;
        #pragma unroll
        for (int qq = 0; qq < 3; qq++) {
            const int m = 4 >> qq;
            float2 cs = C.s_rot[tt * NQ + qb1 + qq];
            u64 C2 = pk(cs.x, cs.x), S2 = pk(cs.y, cs.y), Sn = pk(-cs.y, -cs.y);
            #pragma unroll
            for (int rr = 0; rr < AMPS / 2; rr++) {
                int r0 = ((rr & ~(m - 1)) << 1) | (rr & (m - 1));
                int r1 = r0 | m;
                u64 p0 = psi[r0], p1 = psi[r1];
                psi[r0] = ffma2(Sn, p1, fmul2(C2, p0));
                psi[r1] = ffma2(S2, p0, fmul2(C2, p1));
            }
        }
    }
    const int wbase = (w << 8) | (lh << 6);
    // ---- exchange qubit 0 (w mask 2) WITH layout flip ----
    {
        float2 cs = C.s_rot[tt * NQ + 0];
        // write under entry layout: PAR=0 -> A: p = ll^lh ; PAR=1 -> B: p = r^lh
        #pragma unroll
        for (int r = 0; r < AMPS; r++) {
            const int p = PAR ? (r ^ lh) : (ll ^ lh);
            C.s_x0[wbase | (p << 3) | (r ^ ll)] = psi[r];
        }
        __syncthreads();
        // read under flipped layout: PAR=0 -> B: p = r^lh ; PAR=1 -> A: p = ll^lh
        float so = (w & 2) ? cs.y : -cs.y;
        u64 C2 = pk(cs.x, cs.x), S2 = pk(so, so);
        const int pbase = ((w ^ 2) << 8) | (lh << 6);
        #pragma unroll
        for (int r = 0; r < AMPS; r++) {
            const int p  = PAR ? (ll ^ lh) : (r ^ lh);
            const int lo = (p << 3) | (r ^ ll);
            u64 own = C.s_x0[wbase | lo];
            u64 par = C.s_x0[pbase | lo];
            psi[r] = ffma2(S2, par, fmul2(C2, own));
        }
    }
    // ---- exchange qubit 1 (w mask 1), flipped layout, no flip ----
    {
        float2 cs = C.s_rot[tt * NQ + 1];
        #pragma unroll
        for (int r = 0; r < AMPS; r++) {
            const int p = PAR ? (ll ^ lh) : (r ^ lh);
            C.s_x1[wbase | (p << 3) | (r ^ ll)] = psi[r];
        }
        __syncthreads();
        float so = (w & 1) ? cs.y : -cs.y;
        u64 C2 = pk(cs.x, cs.x), S2 = pk(so, so);
        const int pbase = ((w ^ 1) << 8) | (lh << 6);
        #pragma unroll
        for (int r = 0; r < AMPS; r++) {
            const int p = PAR ? (ll ^ lh) : (r ^ lh);
            u64 par = C.s_x1[pbase | (p << 3) | (r ^ ll)];
            psi[r] = ffma2(S2, par, fmul2(C2, psi[r]));
        }
    }
    // ---- reg triple 2 (flipped layout): the other qubit triple ----
    {
        const int qb2 = PAR ? 4 : 7;
        #pragma unroll
        for (int qq = 0; qq < 3; qq++) {
            const int m = 4 >> qq;
            float2 cs = C.s_rot[tt * NQ + qb2 + qq];
            u64 C2 = pk(cs.x, cs.x), S2 = pk(cs.y, cs.y), Sn = pk(-cs.y, -cs.y);
            #pragma unroll
            for (int rr = 0; rr < AMPS / 2; rr++) {
                int r0 = ((rr & ~(m - 1)) << 1) | (rr & (m - 1));
                int r1 = r0 | m;
                u64 p0 = psi[r0], p1 = psi[r1];
                psi[r0] = ffma2(Sn, p1, fmul2(C2, p0));
                psi[r1] = ffma2(S2, p0, fmul2(C2, p1));
            }
        }
    }
}

__global__ __launch_bounds__(NTHREADS)
void scramble_kernel(const float* __restrict__ in_re,
                     const float* __restrict__ in_im,
                     const float* __restrict__ phis,
                     const float* __restrict__ gs,
                     float* __restrict__ out)
{
    __shared__ u64    s_x[2][DIM];
    __shared__ float2 s_rot[TSTEPS * NQ];     // (cos(th/2), sin(th/2))
    __shared__ float  s_wgt[11][NQ];          // merged diag weights
    __shared__ float  s_lane[11 * 32];        // layout-aware lane sums
    __shared__ float  s_rphi[11 * 8 * 11];    // layout-aware reg sums + popcount phase
    __shared__ float  s_w[11 * 4];            // w sums + (-0.5*total)
    __shared__ float  s_nrm[4];

    const int tid  = threadIdx.x;
    const int w    = tid >> 5;
    const int lane = tid & 31;
    const int lh   = lane >> 3;
    const int ll   = lane & 7;
    const int b    = blockIdx.x;
    const float* P = phis + b * 300;

    // ---- rotation coefficients ----
    if (tid < 100) {
        int tt = tid / NQ, i = tid - tt * NQ;
        float th = P[30 * tt + NQ + i];
        float s, c; __sincosf(0.5f * th, &s, &c);
        s_rot[tid] = make_float2(c, s);
    }
    // ---- merged diag weights w_i(t) = a_i(t) + b_i(t-1) ----
    if (tid < 110) {
        int tt = tid / NQ, i = tid - tt * NQ;
        float v = 0.f;
        if (tt < 10) v += P[30 * tt + i];
        if (tt > 0)  v += P[30 * (tt - 1) + 2 * NQ + i];
        s_wgt[tt][i] = v;
    }
    __syncthreads();
    // ---- lane-sum tables (layout at diag of step tt: A if tt even) ----
    for (int idx = tid; idx < 11 * 32; idx += NTHREADS) {
        int tt = idx >> 5, l = idx & 31, la = tt & 1;
        float s = 0.f;
        if (l & 16) s += s_wgt[tt][2];
        if (l & 8)  s += s_wgt[tt][3];
        if (la == 0) {   // A: lane low bits = b-field -> qubits 7,8,9
            if (l & 4) s += s_wgt[tt][7];
            if (l & 2) s += s_wgt[tt][8];
            if (l & 1) s += s_wgt[tt][9];
        } else {         // B: lane low bits = a-field -> qubits 4,5,6
            if (l & 4) s += s_wgt[tt][4];
            if (l & 2) s += s_wgt[tt][5];
            if (l & 1) s += s_wgt[tt][6];
        }
        s_lane[idx] = s;
    }
    // ---- w-sum tables ----
    for (int idx = tid; idx < 11 * 4; idx += NTHREADS) {
        int tt = idx >> 2, ww = idx & 3;
        float tot = 0.f;
        #pragma unroll
        for (int i = 0; i < NQ; i++) tot += s_wgt[tt][i];
        float s = -0.5f * tot;
        if (ww & 1) s += s_wgt[tt][1];
        if (ww & 2) s += s_wgt[tt][0];
        s_w[idx] = s;
    }
    // ---- reg-sum + popcount-phase tables ----
    for (int idx = tid; idx < 11 * 8 * 11; idx += NTHREADS) {
        int tt = idx / 88, rem = idx - tt * 88;
        int r = rem / 11, k = rem - r * 11, la = tt & 1;
        float v = 0.f;
        if (la == 0) {   // A: r = a-field -> qubits 4,5,6
            if (r & 4) v += s_wgt[tt][4];
            if (r & 2) v += s_wgt[tt][5];
            if (r & 1) v += s_wgt[tt][6];
        } else {         // B: r = b-field -> qubits 7,8,9
            if (r & 4) v += s_wgt[tt][7];
            if (r & 2) v += s_wgt[tt][8];
            if (r & 1) v += s_wgt[tt][9];
        }
        if (tt > 0) {
            const float inv = 0.15811388300841897f;  // 1/(2*sqrt(10))
            float theta = gs[b * TSTEPS + tt - 1] * inv;
            float zs = 10.f - 2.f * (float)k;
            v += -0.5f * theta * (0.5f * (zs * zs - 10.f));
        }
        s_rphi[idx] = v;
    }

    // ---- load amplitudes (layout A) + norm ----
    u64 psi[AMPS];
    float nrm = 0.f;
    #pragma unroll
    for (int r = 0; r < AMPS; r++) {
        int j = (w << 8) | (lh << 6) | (r << 3) | ll;
        float re = in_re[b * DIM + j];
        float im = in_im[b * DIM + j];
        psi[r] = pk(re, im);
        nrm += re * re + im * im;
    }
    #pragma unroll
    for (int off = 16; off; off >>= 1)
        nrm += __shfl_xor_sync(0xFFFFFFFFu, nrm, off);
    if (lane == 0) s_nrm[w] = nrm;
    __syncthreads();                           // also fences table builds
    const float invn = rsqrtf(s_nrm[0] + s_nrm[1] + s_nrm[2] + s_nrm[3]);
    const int k0 = __popc(lane) + __popc(w);

    Ctx C{ s_x[0], s_x[1], s_rot, s_lane, s_rphi, s_w };

    // ---- 10 steps, parity specialized at compile time ----
    #pragma unroll 1
    for (int th = 0; th < TSTEPS / 2; th++) {
        do_step<0>(2 * th,     psi, C, w, lane, lh, ll, k0);
        do_step<1>(2 * th + 1, psi, C, w, lane, lh, ll, k0);
    }

    // ---- final diagonal E_10 (layout A) ----
    {
        float base = s_lane[10 * 32 + lane] + s_w[10 * 4 + w];
        const float* rp = s_rphi + 10 * 88 + k0;
        #pragma unroll
        for (int r = 0; r < AMPS; r++) {
            float ph = base + rp[r * 11 + __popc(r)];
            float sn, cn; __sincosf(ph, &sn, &cn);
            psi[r] = ffma2(pk(-sn, sn), swp(psi[r]), fmul2(pk(cn, cn), psi[r]));
        }
    }
    // ---- store (layout A) with deferred normalization ----
    #pragma unroll
    for (int r = 0; r < AMPS; r++) {
        int j = (w << 8) | (lh << 6) | (r << 3) | ll;
        float x, y; upk(psi[r], x, y);
        out[b * DIM + j]               = x * invn;
        out[NDATA * DIM + b * DIM + j] = y * invn;
    }
}

extern "C" void kernel_launch(void* const* d_in, const int* in_sizes, int n_in,
                              void* d_out, int out_size)
{
    const float* in_re = (const float*)d_in[0];
    const float* in_im = (const float*)d_in[1];
    const float* phis  = (const float*)d_in[2];
    const float* gs    = (const float*)d_in[3];
    float* out = (float*)d_out;
    scramble_kernel<<<NDATA, NTHREADS>>>(in_re, in_im, phis, gs, out);
}

// round 10
// speedup vs baseline: 1.0048x; 1.0038x over previous
#include <cuda_runtime.h>

#define NQ      10
#define DIM     1024
#define TSTEPS  10
#define NDATA   1024
#define NTHREADS 128               // 4 warps = 1 sample
#define AMPS    8

typedef unsigned long long u64;

__device__ __forceinline__ u64 pk(float x, float y) {
    u64 u; asm("mov.b64 %0, {%1,%2};" : "=l"(u) : "f"(x), "f"(y)); return u;
}
__device__ __forceinline__ void upk(u64 u, float &x, float &y) {
    asm("mov.b64 {%0,%1}, %2;" : "=f"(x), "=f"(y) : "l"(u));
}
__device__ __forceinline__ u64 swp(u64 u) { float x, y; upk(u, x, y); return pk(y, x); }
__device__ __forceinline__ u64 ffma2(u64 a, u64 b, u64 c) {
    u64 d; asm("fma.rn.f32x2 %0, %1, %2, %3;" : "=l"(d) : "l"(a), "l"(b), "l"(c)); return d;
}
__device__ __forceinline__ u64 fmul2(u64 a, u64 b) {
    u64 d; asm("mul.rn.f32x2 %0, %1, %2;" : "=l"(d) : "l"(a), "l"(b)); return d;
}

// amp j = (w<<8)|(lh<<6)|(a<<3)|b ; qubit i <-> j bit (9-i)
// Layout A: lane=(lh<<3)|ll, reg r holds amp(a=r, b=ll)  [reg qubits 4,5,6]
// Layout B: lane=(lh<<3)|ll, reg r holds amp(a=ll, b=r)  [reg qubits 7,8,9]
// slot(w,lh,a,b) = (w<<8)|(lh<<6)|((b^lh)<<3)|(a^b)   (conflict-free both layouts)

struct Ctx {
    u64*    s_x0;
    u64*    s_x1;
    float2* s_rot;
    float*  s_lane;
    float*  s_rphi;
    float*  s_w;
};

// One full time step, parity PAR (0: enters layout A; flips mid-step)
template<int PAR>
__device__ __forceinline__ void do_step(int tt, u64 (&psi)[AMPS], const Ctx& C,
                                        int w, int lane, int lh, int ll, int k0)
{
    // ---- diagonal E_tt (entry layout; tables layout-aware) ----
    {
        float base = C.s_lane[tt * 32 + lane] + C.s_w[tt * 4 + w];
        const float* rp = C.s_rphi + tt * 88 + k0;
        #pragma unroll
        for (int r = 0; r < AMPS; r++) {
            float ph = base + rp[r * 11 + __popc(r)];
            float sn, cn; __sincosf(ph, &sn, &cn);
            psi[r] = ffma2(pk(-sn, sn), swp(psi[r]), fmul2(pk(cn, cn), psi[r]));
        }
    }
    // ---- shuffle gates: qubits 2,3 (lane masks 16,8) ----
    #pragma unroll
    for (int q = 2; q < 4; q++) {
        const int m = 1 << (6 - q);
        float2 cs = C.s_rot[tt * NQ + q];
        float so = (lane & m) ? cs.y : -cs.y;
        u64 C2 = pk(cs.x, cs.x), S2 = pk(so, so);
        #pragma unroll
        for (int r = 0; r < AMPS; r++) {
            float x, y; upk(psi[r], x, y);
            float ox = __shfl_xor_sync(0xFFFFFFFFu, x, m);
            float oy = __shfl_xor_sync(0xFFFFFFFFu, y, m);
            psi[r] = ffma2(S2, pk(ox, oy), fmul2(C2, psi[r]));
        }
    }
    // ---- reg triple 1 (entry layout): qubits (PAR?7:4)+qq, masks 4,2,1 ----
    {
        const int qb1 = PAR ? 7 : 4;
        #pragma unroll
        for (int qq = 0; qq < 3; qq++) {
            const int m = 4 >> qq;
            float2 cs = C.s_rot[tt * NQ + qb1 + qq];
            u64 C2 = pk(cs.x, cs.x), S2 = pk(cs.y, cs.y), Sn = pk(-cs.y, -cs.y);
            #pragma unroll
            for (int rr = 0; rr < AMPS / 2; rr++) {
                int r0 = ((rr & ~(m - 1)) << 1) | (rr & (m - 1));
                int r1 = r0 | m;
                u64 p0 = psi[r0], p1 = psi[r1];
                psi[r0] = ffma2(Sn, p1, fmul2(C2, p0));
                psi[r1] = ffma2(S2, p0, fmul2(C2, p1));
            }
        }
    }
    // ---- combined q0 (x) q1 4-way exchange WITH layout flip, 1 barrier ----
    {
        u64* buf = PAR ? C.s_x1 : C.s_x0;
        float2 cs0 = C.s_rot[tt * NQ + 0];   // qubit 0 = w bit 1
        float2 cs1 = C.s_rot[tt * NQ + 1];   // qubit 1 = w bit 0
        const int x1 = (w >> 1) & 1;
        const int x0 = w & 1;
        float g0a = cs0.x, g0b = x1 ? cs0.y : -cs0.y;   // own / other along q0
        float g1a = cs1.x, g1b = x0 ? cs1.y : -cs1.y;   // own / other along q1
        // K[w'] = R0[x1][w'>>1] * R1[x0][w'&1]
        float k0c = (x1 == 0 ? g0a : g0b) * (x0 == 0 ? g1a : g1b);
        float k1c = (x1 == 0 ? g0a : g0b) * (x0 == 1 ? g1a : g1b);
        float k2c = (x1 == 1 ? g0a : g0b) * (x0 == 0 ? g1a : g1b);
        float k3c = (x1 == 1 ? g0a : g0b) * (x0 == 1 ? g1a : g1b);
        u64 K0 = pk(k0c, k0c), K1 = pk(k1c, k1c), K2 = pk(k2c, k2c), K3 = pk(k3c, k3c);

        // write under entry layout
        const int wbase = (w << 8) | (lh << 6);
        #pragma unroll
        for (int r = 0; r < AMPS; r++) {
            const int p = PAR ? (r ^ lh) : (ll ^ lh);
            buf[wbase | (p << 3) | (r ^ ll)] = psi[r];
        }
        __syncthreads();
        // read all 4 w-partners under flipped layout, combine
        #pragma unroll
        for (int r = 0; r < AMPS; r++) {
            const int p  = PAR ? (ll ^ lh) : (r ^ lh);
            const int lo = (lh << 6) | (p << 3) | (r ^ ll);
            u64 acc =  fmul2(K0, buf[lo]);
            acc = ffma2(K1, buf[(1 << 8) | lo], acc);
            acc = ffma2(K2, buf[(2 << 8) | lo], acc);
            acc = ffma2(K3, buf[(3 << 8) | lo], acc);
            psi[r] = acc;
        }
    }
    // ---- reg triple 2 (flipped layout): the other qubit triple ----
    {
        const int qb2 = PAR ? 4 : 7;
        #pragma unroll
        for (int qq = 0; qq < 3; qq++) {
            const int m = 4 >> qq;
            float2 cs = C.s_rot[tt * NQ + qb2 + qq];
            u64 C2 = pk(cs.x, cs.x), S2 = pk(cs.y, cs.y), Sn = pk(-cs.y, -cs.y);
            #pragma unroll
            for (int rr = 0; rr < AMPS / 2; rr++) {
                int r0 = ((rr & ~(m - 1)) << 1) | (rr & (m - 1));
                int r1 = r0 | m;
                u64 p0 = psi[r0], p1 = psi[r1];
                psi[r0] = ffma2(Sn, p1, fmul2(C2, p0));
                psi[r1] = ffma2(S2, p0, fmul2(C2, p1));
            }
        }
    }
}

__global__ __launch_bounds__(NTHREADS, 8)
void scramble_kernel(const float* __restrict__ in_re,
                     const float* __restrict__ in_im,
                     const float* __restrict__ phis,
                     const float* __restrict__ gs,
                     float* __restrict__ out)
{
    __shared__ u64    s_x[2][DIM];
    __shared__ float2 s_rot[TSTEPS * NQ];     // (cos(th/2), sin(th/2))
    __shared__ float  s_wgt[11][NQ];          // merged diag weights
    __shared__ float  s_lane[11 * 32];        // layout-aware lane sums
    __shared__ float  s_rphi[11 * 8 * 11];    // layout-aware reg sums + popcount phase
    __shared__ float  s_w[11 * 4];            // w sums + (-0.5*total)
    __shared__ float  s_nrm[4];

    const int tid  = threadIdx.x;
    const int w    = tid >> 5;
    const int lane = tid & 31;
    const int lh   = lane >> 3;
    const int ll   = lane & 7;
    const int b    = blockIdx.x;
    const float* P = phis + b * 300;

    // ---- rotation coefficients ----
    if (tid < 100) {
        int tt = tid / NQ, i = tid - tt * NQ;
        float th = P[30 * tt + NQ + i];
        float s, c; __sincosf(0.5f * th, &s, &c);
        s_rot[tid] = make_float2(c, s);
    }
    // ---- merged diag weights w_i(t) = a_i(t) + b_i(t-1) ----
    if (tid < 110) {
        int tt = tid / NQ, i = tid - tt * NQ;
        float v = 0.f;
        if (tt < 10) v += P[30 * tt + i];
        if (tt > 0)  v += P[30 * (tt - 1) + 2 * NQ + i];
        s_wgt[tt][i] = v;
    }
    __syncthreads();
    // ---- lane-sum tables (entry layout of step tt: A if tt even) ----
    for (int idx = tid; idx < 11 * 32; idx += NTHREADS) {
        int tt = idx >> 5, l = idx & 31, la = tt & 1;
        float s = 0.f;
        if (l & 16) s += s_wgt[tt][2];
        if (l & 8)  s += s_wgt[tt][3];
        if (la == 0) {   // A: lane low bits = b-field -> qubits 7,8,9
            if (l & 4) s += s_wgt[tt][7];
            if (l & 2) s += s_wgt[tt][8];
            if (l & 1) s += s_wgt[tt][9];
        } else {         // B: lane low bits = a-field -> qubits 4,5,6
            if (l & 4) s += s_wgt[tt][4];
            if (l & 2) s += s_wgt[tt][5];
            if (l & 1) s += s_wgt[tt][6];
        }
        s_lane[idx] = s;
    }
    // ---- w-sum tables ----
    for (int idx = tid; idx < 11 * 4; idx += NTHREADS) {
        int tt = idx >> 2, ww = idx & 3;
        float tot = 0.f;
        #pragma unroll
        for (int i = 0; i < NQ; i++) tot += s_wgt[tt][i];
        float s = -0.5f * tot;
        if (ww & 1) s += s_wgt[tt][1];
        if (ww & 2) s += s_wgt[tt][0];
        s_w[idx] = s;
    }
    // ---- reg-sum + popcount-phase tables ----
    for (int idx = tid; idx < 11 * 8 * 11; idx += NTHREADS) {
        int tt = idx / 88, rem = idx - tt * 88;
        int r = rem / 11, k = rem - r * 11, la = tt & 1;
        float v = 0.f;
        if (la == 0) {   // A: r = a-field -> qubits 4,5,6
            if (r & 4) v += s_wgt[tt][4];
            if (r & 2) v += s_wgt[tt][5];
            if (r & 1) v += s_wgt[tt][6];
        } else {         // B: r = b-field -> qubits 7,8,9
            if (r & 4) v += s_wgt[tt][7];
            if (r & 2) v += s_wgt[tt][8];
            if (r & 1) v += s_wgt[tt][9];
        }
        if (tt > 0) {
            const float inv = 0.15811388300841897f;  // 1/(2*sqrt(10))
            float theta = gs[b * TSTEPS + tt - 1] * inv;
            float zs = 10.f - 2.f * (float)k;
            v += -0.5f * theta * (0.5f * (zs * zs - 10.f));
        }
        s_rphi[idx] = v;
    }

    // ---- load amplitudes (layout A) + norm ----
    u64 psi[AMPS];
    float nrm = 0.f;
    #pragma unroll
    for (int r = 0; r < AMPS; r++) {
        int j = (w << 8) | (lh << 6) | (r << 3) | ll;
        float re = in_re[b * DIM + j];
        float im = in_im[b * DIM + j];
        psi[r] = pk(re, im);
        nrm += re * re + im * im;
    }
    #pragma unroll
    for (int off = 16; off; off >>= 1)
        nrm += __shfl_xor_sync(0xFFFFFFFFu, nrm, off);
    if (lane == 0) s_nrm[w] = nrm;
    __syncthreads();                           // also fences table builds
    const float invn = rsqrtf(s_nrm[0] + s_nrm[1] + s_nrm[2] + s_nrm[3]);
    const int k0 = __popc(lane) + __popc(w);

    Ctx C{ s_x[0], s_x[1], s_rot, s_lane, s_rphi, s_w };

    // ---- 10 steps, parity specialized; one barrier per step ----
    #pragma unroll 1
    for (int th = 0; th < TSTEPS / 2; th++) {
        do_step<0>(2 * th,     psi, C, w, lane, lh, ll, k0);
        do_step<1>(2 * th + 1, psi, C, w, lane, lh, ll, k0);
    }

    // ---- final diagonal E_10 (layout A) ----
    {
        float base = s_lane[10 * 32 + lane] + s_w[10 * 4 + w];
        const float* rp = s_rphi + 10 * 88 + k0;
        #pragma unroll
        for (int r = 0; r < AMPS; r++) {
            float ph = base + rp[r * 11 + __popc(r)];
            float sn, cn; __sincosf(ph, &sn, &cn);
            psi[r] = ffma2(pk(-sn, sn), swp(psi[r]), fmul2(pk(cn, cn), psi[r]));
        }
    }
    // ---- store (layout A) with deferred normalization ----
    #pragma unroll
    for (int r = 0; r < AMPS; r++) {
        int j = (w << 8) | (lh << 6) | (r << 3) | ll;
        float x, y; upk(psi[r], x, y);
        out[b * DIM + j]               = x * invn;
        out[NDATA * DIM + b * DIM + j] = y * invn;
    }
}

extern "C" void kernel_launch(void* const* d_in, const int* in_sizes, int n_in,
                              void* d_out, int out_size)
{
    const float* in_re = (const float*)d_in[0];
    const float* in_im = (const float*)d_in[1];
    const float* phis  = (const float*)d_in[2];
    const float* gs    = (const float*)d_in[3];
    float* out = (float*)d_out;
    scramble_kernel<<<NDATA, NTHREADS>>>(in_re, in_im, phis, gs, out);
}